// round 3
// baseline (speedup 1.0000x reference)
#include <cuda_runtime.h>

#define BATCH 4
#define DS 16
#define NO 2048
#define NR 16384
#define DR 8
#define DE 64
#define DX 8
#define DP 64
#define NC 10

typedef unsigned long long u64;

// Scratch (allocation-free rule: __device__ globals)
__device__ float g_E[(size_t)BATCH * DE * NR];   // (B, DE, NR)  16.8 MB
__device__ float g_Eh[(size_t)BATCH * DE * NO];  // (B, DE, NO)   2 MB

// ---- packed fp32x2 helpers (Blackwell FFMA2; PTX-only path) ----
__device__ __forceinline__ u64 ffma2(u64 a, u64 b, u64 c) {
    u64 d;
    asm("fma.rn.f32x2 %0, %1, %2, %3;" : "=l"(d) : "l"(a), "l"(b), "l"(c));
    return d;
}
__device__ __forceinline__ u64 pack2(float lo, float hi) {
    u64 r;
    asm("mov.b64 %0, {%1, %2};" : "=l"(r) : "f"(lo), "f"(hi));
    return r;
}
__device__ __forceinline__ float2 unpack2(u64 v) {
    float2 f;
    asm("mov.b64 {%0, %1}, %2;" : "=f"(f.x), "=f"(f.y) : "l"(v));
    return f;
}

// ============================================================================
// Kernel A: E = W_r @ [O@R_s ; O@R_r ; R_a] + b_r        (B, DE, NR)
// grid (NR/512, BATCH), block 512. One thread owns one relation column r.
// O staged in smem as (d,d+1) f32x2 pairs, broadcast-read per o.
// ============================================================================
__global__ void __launch_bounds__(512, 1)
kernelA(const float* __restrict__ O, const float* __restrict__ Rs,
        const float* __restrict__ Rr, const float* __restrict__ Ra,
        const float* __restrict__ Wr, const float* __restrict__ br)
{
    extern __shared__ u64 sm[];
    u64* sO = sm;                       // [NO][8] d-pairs
    u64* sW = sm + (size_t)NO * 8;      // [DE][20] f-pairs
    float* sbr = (float*)(sW + DE * 20);

    const int tid = threadIdx.x;
    const int b   = blockIdx.y;
    const int r   = blockIdx.x * 512 + tid;

    // stage O (16 x 2048) as pairs over d
    const float* Ob = O + (size_t)b * DS * NO;
    for (int idx = tid; idx < 8 * NO; idx += 512) {
        int d2 = idx / NO, o = idx - d2 * NO;
        sO[(size_t)o * 8 + d2] = pack2(Ob[(size_t)(2 * d2) * NO + o],
                                       Ob[(size_t)(2 * d2 + 1) * NO + o]);
    }
    // stage W_r (64 x 40) as pairs over f
    for (int idx = tid; idx < DE * 20; idx += 512) {
        int e = idx / 20, f2 = idx - e * 20;
        float2 w = *(const float2*)(Wr + (size_t)e * 40 + 2 * f2);
        sW[(size_t)e * 20 + f2] = pack2(w.x, w.y);
    }
    if (tid < DE) sbr[tid] = br[tid];
    __syncthreads();

    const float* ps = Rs + (size_t)b * NO * NR + r;
    const float* pr = Rr + (size_t)b * NO * NR + r;

    u64 m1[8], m2[8];
#pragma unroll
    for (int i = 0; i < 8; i++) { m1[i] = 0ull; m2[i] = 0ull; }

    const int U = 8;
    float as[2][U], ar[2][U];
#pragma unroll
    for (int u = 0; u < U; u++) {
        as[0][u] = ps[(size_t)u * NR];
        ar[0][u] = pr[(size_t)u * NR];
    }
    int buf = 0;
    for (int o = 0; o < NO; o += U) {
        int nb = buf ^ 1;
        if (o + U < NO) {
#pragma unroll
            for (int u = 0; u < U; u++) {
                as[nb][u] = ps[(size_t)(o + U + u) * NR];
                ar[nb][u] = pr[(size_t)(o + U + u) * NR];
            }
        }
#pragma unroll
        for (int u = 0; u < U; u++) {
            u64 bs  = pack2(as[buf][u], as[buf][u]);
            u64 brr = pack2(ar[buf][u], ar[buf][u]);
            const u64* orow = sO + (size_t)(o + u) * 8;
#pragma unroll
            for (int d2 = 0; d2 < 8; d2++) {
                u64 ov = orow[d2];
                m1[d2] = ffma2(ov, bs,  m1[d2]);
                m2[d2] = ffma2(ov, brr, m2[d2]);
            }
        }
        buf = nb;
    }

    // R_a pairs
    const float* Rab = Ra + (size_t)b * DR * NR + r;
    u64 rap[4];
#pragma unroll
    for (int j = 0; j < 4; j++)
        rap[j] = pack2(Rab[(size_t)(2 * j) * NR], Rab[(size_t)(2 * j + 1) * NR]);

    // E = W_r @ B + b_r  (dot over 40 features as 20 packed pairs)
    float* Eb = g_E + (size_t)b * DE * NR + r;
#pragma unroll 4
    for (int e = 0; e < DE; e++) {
        const u64* wrow = sW + (size_t)e * 20;
        u64 acc = 0ull;
#pragma unroll
        for (int f2 = 0; f2 < 8; f2++)  acc = ffma2(wrow[f2],      m1[f2],  acc);
#pragma unroll
        for (int f2 = 0; f2 < 8; f2++)  acc = ffma2(wrow[8 + f2],  m2[f2],  acc);
#pragma unroll
        for (int j = 0; j < 4; j++)     acc = ffma2(wrow[16 + j],  rap[j],  acc);
        float2 a = unpack2(acc);
        Eb[(size_t)e * NR] = a.x + a.y + sbr[e];
    }
}

// ============================================================================
// Kernel B: E_hat[b,e,o] = sum_r E[b,e,r] * R_r[b,o,r]     (B, DE, NO)
// grid (NO/64, BATCH), block 256. CTA tile 64e x 64o, K-chunk 64, reg-staged
// prefetch, smem tiles transposed to [r][*] for broadcast/packed LDS.
// ============================================================================
#define KC 64
#define PE 68   // sE pitch (floats), 16B-aligned rows
#define PR 66   // sR pitch (floats), 8B-aligned rows

__global__ void __launch_bounds__(256, 1)
kernelB(const float* __restrict__ Rr)
{
    __shared__ __align__(16) float sE[KC * PE];  // [rr][e]
    __shared__ __align__(16) float sR[KC * PR];  // [rr][o]

    const int tid = threadIdx.x;
    const int b   = blockIdx.y;
    const int o0  = blockIdx.x * 64;
    const int tx  = tid & 15;   // o quad
    const int ty  = tid >> 4;   // e quad

    const float* Eg = g_E + (size_t)b * DE * NR;
    const float* Rg = Rr  + (size_t)b * NO * NR;

    u64 acc[4][2];
#pragma unroll
    for (int i = 0; i < 4; i++) { acc[i][0] = 0ull; acc[i][1] = 0ull; }

    float stE[16], stR[16];
    // prologue: chunk 0 -> regs
#pragma unroll
    for (int k = 0; k < 16; k++) {
        int idx = tid + k * 256;
        int rr = idx & 63, c = idx >> 6;
        stE[k] = Eg[(size_t)c * NR + rr];
        stR[k] = Rg[(size_t)(o0 + c) * NR + rr];
    }

    for (int kc = 0; kc < NR / KC; kc++) {
        // regs -> smem (transposed)
#pragma unroll
        for (int k = 0; k < 16; k++) {
            int idx = tid + k * 256;
            int rr = idx & 63, c = idx >> 6;
            sE[rr * PE + c] = stE[k];
            sR[rr * PR + c] = stR[k];
        }
        __syncthreads();

        // prefetch next chunk into regs (latency hidden under compute)
        if (kc + 1 < NR / KC) {
            int rc = (kc + 1) * KC;
#pragma unroll
            for (int k = 0; k < 16; k++) {
                int idx = tid + k * 256;
                int rr = idx & 63, c = idx >> 6;
                stE[k] = Eg[(size_t)c * NR + rc + rr];
                stR[k] = Rg[(size_t)(o0 + c) * NR + rc + rr];
            }
        }

        // compute: 8 FFMA2 per r-step per lane (4e x 4o outputs)
#pragma unroll 16
        for (int rr = 0; rr < KC; rr++) {
            float4 ev = *(const float4*)&sE[rr * PE + ty * 4];
            u64 r01 = *(const u64*)&sR[rr * PR + tx * 4];
            u64 r23 = *(const u64*)&sR[rr * PR + tx * 4 + 2];
            u64 e0 = pack2(ev.x, ev.x);
            u64 e1 = pack2(ev.y, ev.y);
            u64 e2 = pack2(ev.z, ev.z);
            u64 e3 = pack2(ev.w, ev.w);
            acc[0][0] = ffma2(e0, r01, acc[0][0]); acc[0][1] = ffma2(e0, r23, acc[0][1]);
            acc[1][0] = ffma2(e1, r01, acc[1][0]); acc[1][1] = ffma2(e1, r23, acc[1][1]);
            acc[2][0] = ffma2(e2, r01, acc[2][0]); acc[2][1] = ffma2(e2, r23, acc[2][1]);
            acc[3][0] = ffma2(e3, r01, acc[3][0]); acc[3][1] = ffma2(e3, r23, acc[3][1]);
        }
        __syncthreads();
    }

    float* out = g_Eh + ((size_t)b * DE + ty * 4) * NO + o0 + tx * 4;
#pragma unroll
    for (int i = 0; i < 4; i++) {
        float2 a = unpack2(acc[i][0]);
        float2 c2 = unpack2(acc[i][1]);
        *(float4*)(out + (size_t)i * NO) = make_float4(a.x, a.y, c2.x, c2.y);
    }
}

// ============================================================================
// Kernel C: P = W_o@[O;X;E_hat]+b_o ; scores = W_s@P+b_s ; softmax over C
// grid (NO/256, BATCH), block 256. Thread per object column.
// ============================================================================
__global__ void __launch_bounds__(256, 1)
kernelC(const float* __restrict__ O, const float* __restrict__ X,
        const float* __restrict__ Wo, const float* __restrict__ bo,
        const float* __restrict__ Ws, const float* __restrict__ bs,
        float* __restrict__ out)
{
    __shared__ u64 sWo[88 * 32];   // [f][p-pair]
    __shared__ u64 sWs[NC * 32];   // [c][p-pair]
    __shared__ float sbo[DP];
    __shared__ float sbs[NC];

    const int tid = threadIdx.x;
    const int b   = blockIdx.y;
    const int o   = blockIdx.x * 256 + tid;

    for (int idx = tid; idx < 88 * 32; idx += 256) {
        int f = idx >> 5, p2 = idx & 31;
        sWo[f * 32 + p2] = pack2(Wo[(size_t)(2 * p2) * 88 + f],
                                 Wo[(size_t)(2 * p2 + 1) * 88 + f]);
    }
    for (int idx = tid; idx < NC * 32; idx += 256) {
        int c = idx >> 5, p2 = idx & 31;
        float2 w = *(const float2*)(Ws + (size_t)c * DP + 2 * p2);
        sWs[c * 32 + p2] = pack2(w.x, w.y);
    }
    if (tid < DP) sbo[tid] = bo[tid];
    if (tid < NC) sbs[tid] = bs[tid];
    __syncthreads();

    u64 P[32];
#pragma unroll
    for (int p2 = 0; p2 < 32; p2++) P[p2] = pack2(sbo[2 * p2], sbo[2 * p2 + 1]);

    const float* Ob  = O    + (size_t)b * DS * NO + o;
    const float* Xb  = X    + (size_t)b * DX * NO + o;
    const float* Ehb = g_Eh + (size_t)b * DE * NO + o;

#pragma unroll 4
    for (int f = 0; f < DS; f++) {
        float cf = Ob[(size_t)f * NO];
        u64 c2 = pack2(cf, cf);
        const u64* wrow = sWo + f * 32;
#pragma unroll
        for (int p2 = 0; p2 < 32; p2++) P[p2] = ffma2(wrow[p2], c2, P[p2]);
    }
#pragma unroll 4
    for (int f = 0; f < DX; f++) {
        float cf = Xb[(size_t)f * NO];
        u64 c2 = pack2(cf, cf);
        const u64* wrow = sWo + (DS + f) * 32;
#pragma unroll
        for (int p2 = 0; p2 < 32; p2++) P[p2] = ffma2(wrow[p2], c2, P[p2]);
    }
#pragma unroll 4
    for (int f = 0; f < DE; f++) {
        float cf = Ehb[(size_t)f * NO];
        u64 c2 = pack2(cf, cf);
        const u64* wrow = sWo + (DS + DX + f) * 32;
#pragma unroll
        for (int p2 = 0; p2 < 32; p2++) P[p2] = ffma2(wrow[p2], c2, P[p2]);
    }

    float sc[NC];
#pragma unroll
    for (int c = 0; c < NC; c++) {
        const u64* wrow = sWs + c * 32;
        u64 acc = 0ull;
#pragma unroll
        for (int p2 = 0; p2 < 32; p2++) acc = ffma2(wrow[p2], P[p2], acc);
        float2 a = unpack2(acc);
        sc[c] = a.x + a.y + sbs[c];
    }

    float mx = sc[0];
#pragma unroll
    for (int c = 1; c < NC; c++) mx = fmaxf(mx, sc[c]);
    float sum = 0.f;
#pragma unroll
    for (int c = 0; c < NC; c++) { sc[c] = expf(sc[c] - mx); sum += sc[c]; }
    float inv = 1.f / sum;
#pragma unroll
    for (int c = 0; c < NC; c++)
        out[((size_t)b * NC + c) * NO + o] = sc[c] * inv;
}

// ============================================================================
extern "C" void kernel_launch(void* const* d_in, const int* in_sizes, int n_in,
                              void* d_out, int out_size)
{
    const float* O  = (const float*)d_in[0];
    const float* Rs = (const float*)d_in[1];
    const float* Rr = (const float*)d_in[2];
    const float* Ra = (const float*)d_in[3];
    const float* X  = (const float*)d_in[4];
    const float* Wr = (const float*)d_in[5];
    const float* br = (const float*)d_in[6];
    const float* Wo = (const float*)d_in[7];
    const float* bo = (const float*)d_in[8];
    const float* Ws = (const float*)d_in[9];
    const float* bs = (const float*)d_in[10];
    float* out = (float*)d_out;
    (void)in_sizes; (void)n_in; (void)out_size;

    // Kernel A dynamic smem: O pairs + W_r pairs + b_r
    int smA = NO * 8 * 8 + DE * 20 * 8 + DE * 4;  // 131072 + 10240 + 256
    cudaFuncSetAttribute(kernelA, cudaFuncAttributeMaxDynamicSharedMemorySize, smA);

    kernelA<<<dim3(NR / 512, BATCH), 512, smA>>>(O, Rs, Rr, Ra, Wr, br);
    kernelB<<<dim3(NO / 64, BATCH), 256>>>(Rr);
    kernelC<<<dim3(NO / 256, BATCH), 256>>>(O, X, Wo, bo, Ws, bs, out);
}

// round 4
// speedup vs baseline: 1.0872x; 1.0872x over previous
#include <cuda_runtime.h>

#define BATCH 4
#define DS 16
#define NO 2048
#define NR 16384
#define DR 8
#define DE 64
#define DX 8
#define DP 64
#define NC 10

#define RSPLIT 8
#define NRS (NR / RSPLIT)   // 2048 r per split

typedef unsigned long long u64;

// Scratch (allocation-free rule: __device__ globals)
__device__ float g_E[(size_t)BATCH * DE * NR];                     // 16.8 MB
__device__ float g_Ehp[(size_t)RSPLIT * BATCH * DE * NO];          // 16.8 MB partials

// ---- packed fp32x2 helpers (Blackwell FFMA2; PTX-only path) ----
__device__ __forceinline__ u64 ffma2(u64 a, u64 b, u64 c) {
    u64 d;
    asm("fma.rn.f32x2 %0, %1, %2, %3;" : "=l"(d) : "l"(a), "l"(b), "l"(c));
    return d;
}
__device__ __forceinline__ u64 pack2(float lo, float hi) {
    u64 r;
    asm("mov.b64 %0, {%1, %2};" : "=l"(r) : "f"(lo), "f"(hi));
    return r;
}
__device__ __forceinline__ float2 unpack2(u64 v) {
    float2 f;
    asm("mov.b64 {%0, %1}, %2;" : "=f"(f.x), "=f"(f.y) : "l"(v));
    return f;
}

// ============================================================================
// Kernel A: E = W_r @ [O@R_s ; O@R_r ; R_a] + b_r        (B, DE, NR)
// grid (NR/512, BATCH), block 512. One thread owns one relation column r.
// O staged in smem as d-pairs; read 4x LDS.128 (broadcast) per o.
// ============================================================================
__global__ void __launch_bounds__(512, 1)
kernelA(const float* __restrict__ O, const float* __restrict__ Rs,
        const float* __restrict__ Rr, const float* __restrict__ Ra,
        const float* __restrict__ Wr, const float* __restrict__ br)
{
    extern __shared__ u64 sm[];
    u64* sO = sm;                       // [NO][8] d-pairs (= [NO][4] ulonglong2)
    u64* sW = sm + (size_t)NO * 8;      // [DE][20] f-pairs
    float* sbr = (float*)(sW + DE * 20);

    const int tid = threadIdx.x;
    const int b   = blockIdx.y;
    const int r   = blockIdx.x * 512 + tid;

    // stage O (16 x 2048) as pairs over d
    const float* Ob = O + (size_t)b * DS * NO;
    for (int idx = tid; idx < 8 * NO; idx += 512) {
        int d2 = idx / NO, o = idx - d2 * NO;
        sO[(size_t)o * 8 + d2] = pack2(Ob[(size_t)(2 * d2) * NO + o],
                                       Ob[(size_t)(2 * d2 + 1) * NO + o]);
    }
    // stage W_r (64 x 40) as pairs over f
    for (int idx = tid; idx < DE * 20; idx += 512) {
        int e = idx / 20, f2 = idx - e * 20;
        float2 w = *(const float2*)(Wr + (size_t)e * 40 + 2 * f2);
        sW[(size_t)e * 20 + f2] = pack2(w.x, w.y);
    }
    if (tid < DE) sbr[tid] = br[tid];
    __syncthreads();

    const float* ps = Rs + (size_t)b * NO * NR + r;
    const float* pr = Rr + (size_t)b * NO * NR + r;

    u64 m1[8], m2[8];
#pragma unroll
    for (int i = 0; i < 8; i++) { m1[i] = 0ull; m2[i] = 0ull; }

    const int U = 8;
    float as[2][U], ar[2][U];
#pragma unroll
    for (int u = 0; u < U; u++) {
        as[0][u] = ps[(size_t)u * NR];
        ar[0][u] = pr[(size_t)u * NR];
    }
    int buf = 0;
    for (int o = 0; o < NO; o += U) {
        int nb = buf ^ 1;
        if (o + U < NO) {
#pragma unroll
            for (int u = 0; u < U; u++) {
                as[nb][u] = ps[(size_t)(o + U + u) * NR];
                ar[nb][u] = pr[(size_t)(o + U + u) * NR];
            }
        }
#pragma unroll
        for (int u = 0; u < U; u++) {
            u64 bs  = pack2(as[buf][u], as[buf][u]);
            u64 brr = pack2(ar[buf][u], ar[buf][u]);
            const ulonglong2* orow = (const ulonglong2*)(sO + (size_t)(o + u) * 8);
            ulonglong2 q0 = orow[0];
            ulonglong2 q1 = orow[1];
            ulonglong2 q2 = orow[2];
            ulonglong2 q3 = orow[3];
            m1[0] = ffma2(q0.x, bs,  m1[0]);  m2[0] = ffma2(q0.x, brr, m2[0]);
            m1[1] = ffma2(q0.y, bs,  m1[1]);  m2[1] = ffma2(q0.y, brr, m2[1]);
            m1[2] = ffma2(q1.x, bs,  m1[2]);  m2[2] = ffma2(q1.x, brr, m2[2]);
            m1[3] = ffma2(q1.y, bs,  m1[3]);  m2[3] = ffma2(q1.y, brr, m2[3]);
            m1[4] = ffma2(q2.x, bs,  m1[4]);  m2[4] = ffma2(q2.x, brr, m2[4]);
            m1[5] = ffma2(q2.y, bs,  m1[5]);  m2[5] = ffma2(q2.y, brr, m2[5]);
            m1[6] = ffma2(q3.x, bs,  m1[6]);  m2[6] = ffma2(q3.x, brr, m2[6]);
            m1[7] = ffma2(q3.y, bs,  m1[7]);  m2[7] = ffma2(q3.y, brr, m2[7]);
        }
        buf = nb;
    }

    // R_a pairs
    const float* Rab = Ra + (size_t)b * DR * NR + r;
    u64 rap[4];
#pragma unroll
    for (int j = 0; j < 4; j++)
        rap[j] = pack2(Rab[(size_t)(2 * j) * NR], Rab[(size_t)(2 * j + 1) * NR]);

    // E = W_r @ B + b_r  (dot over 40 features as 20 packed pairs)
    float* Eb = g_E + (size_t)b * DE * NR + r;
#pragma unroll 4
    for (int e = 0; e < DE; e++) {
        const u64* wrow = sW + (size_t)e * 20;
        u64 acc = 0ull;
#pragma unroll
        for (int f2 = 0; f2 < 8; f2++)  acc = ffma2(wrow[f2],      m1[f2],  acc);
#pragma unroll
        for (int f2 = 0; f2 < 8; f2++)  acc = ffma2(wrow[8 + f2],  m2[f2],  acc);
#pragma unroll
        for (int j = 0; j < 4; j++)     acc = ffma2(wrow[16 + j],  rap[j],  acc);
        float2 a = unpack2(acc);
        Eb[(size_t)e * NR] = a.x + a.y + sbr[e];
    }
}

// ============================================================================
// Kernel B: E_hat[e,o] += sum_{r in split} E[e,r] * R_r[o,r]
// grid (NO/128, BATCH, RSPLIT) = 512 CTAs, block 128 (4 warps), 4 CTAs/SM.
// CTA tile 64e x 128o over 2048 r. Thread tile 8e x 8o (32 FFMA2 / rr).
// sR2 holds DUPLICATED (v,v) pairs -> FFMA2 broadcast operand is one LDS.64,
// no register-duplication MOVs in the inner loop.
// ============================================================================
#define KCB 32
#define PEB 68    // sE pitch (floats): 16B-aligned rows, conflict-free
#define PRB 258   // sR2 pitch (floats)

__global__ void __launch_bounds__(128, 4)
kernelB(const float* __restrict__ Rr)
{
    __shared__ __align__(16) float sE[KCB * PEB];    // [rr][e]        8.7 KB
    __shared__ __align__(16) float sR2[KCB * PRB];   // [rr][2*o] dup 33.0 KB

    const int tid = threadIdx.x;
    const int tx  = tid & 15;     // o group: o = o0 + tx + 16j
    const int ty  = tid >> 4;     // 0..7 : e = 8*ty + 0..7
    const int o0  = blockIdx.x * 128;
    const int b   = blockIdx.y;
    const int rb0 = blockIdx.z * NRS;

    const float* Eg = g_E + (size_t)b * DE * NR;
    const float* Rg = Rr  + (size_t)b * NO * NR;

    u64 acc[4][8];
#pragma unroll
    for (int i = 0; i < 4; i++)
#pragma unroll
        for (int j = 0; j < 8; j++) acc[i][j] = 0ull;

    // staging maps
    const int eS = tid & 63;      // E row this thread stages
    const int hS = tid >> 6;      // rr half (0/1), 16 rr each

    for (int kc = 0; kc < NRS / KCB; kc++) {
        const int rbase = rb0 + kc * KCB;

        // ---- global loads into regs (issued before the barrier) ----
        float4 ev[4];
        {
            const float4* ep = (const float4*)(Eg + (size_t)eS * NR + rbase + hS * 16);
#pragma unroll
            for (int q = 0; q < 4; q++) ev[q] = ep[q];
        }
        float4 rv[8];
        {
            const float4* rp = (const float4*)(Rg + (size_t)(o0 + tid) * NR + rbase);
#pragma unroll
            for (int q = 0; q < 8; q++) rv[q] = rp[q];
        }

        __syncthreads();   // previous chunk's compute done before overwrite

        // ---- stores: sE transposed [rr][e]; sR2 duplicated pairs [rr][2o] ----
#pragma unroll
        for (int q = 0; q < 4; q++) {
            int k = hS * 16 + 4 * q;
            sE[(k + 0) * PEB + eS] = ev[q].x;
            sE[(k + 1) * PEB + eS] = ev[q].y;
            sE[(k + 2) * PEB + eS] = ev[q].z;
            sE[(k + 3) * PEB + eS] = ev[q].w;
        }
#pragma unroll
        for (int q = 0; q < 8; q++) {
            int k = 4 * q;
            *(float2*)&sR2[(k + 0) * PRB + 2 * tid] = make_float2(rv[q].x, rv[q].x);
            *(float2*)&sR2[(k + 1) * PRB + 2 * tid] = make_float2(rv[q].y, rv[q].y);
            *(float2*)&sR2[(k + 2) * PRB + 2 * tid] = make_float2(rv[q].z, rv[q].z);
            *(float2*)&sR2[(k + 3) * PRB + 2 * tid] = make_float2(rv[q].w, rv[q].w);
        }
        __syncthreads();

        // ---- compute: per rr: 2 LDS.128 (E pairs) + 8 LDS.64 (R dup) + 32 FFMA2
#pragma unroll 4
        for (int rr = 0; rr < KCB; rr++) {
            ulonglong2 e01 = *(const ulonglong2*)&sE[rr * PEB + 8 * ty];
            ulonglong2 e23 = *(const ulonglong2*)&sE[rr * PEB + 8 * ty + 4];
#pragma unroll
            for (int j = 0; j < 8; j++) {
                u64 rj = *(const u64*)&sR2[rr * PRB + 2 * tx + 32 * j];
                acc[0][j] = ffma2(e01.x, rj, acc[0][j]);
                acc[1][j] = ffma2(e01.y, rj, acc[1][j]);
                acc[2][j] = ffma2(e23.x, rj, acc[2][j]);
                acc[3][j] = ffma2(e23.y, rj, acc[3][j]);
            }
        }
    }

    // ---- write partial tile ----
    float* out = g_Ehp + (((size_t)blockIdx.z * BATCH + b) * DE) * NO;
#pragma unroll
    for (int ep = 0; ep < 4; ep++) {
        int e = 8 * ty + 2 * ep;
#pragma unroll
        for (int j = 0; j < 8; j++) {
            float2 v = unpack2(acc[ep][j]);
            int o = o0 + tx + 16 * j;
            out[(size_t)e * NO + o]       = v.x;
            out[(size_t)(e + 1) * NO + o] = v.y;
        }
    }
}

// ============================================================================
// Kernel C: P = W_o@[O;X;sum_s E_hat_s]+b_o ; scores = W_s@P+b_s ; softmax
// grid (NO/256, BATCH), block 256. Thread per object column.
// ============================================================================
__global__ void __launch_bounds__(256, 1)
kernelC(const float* __restrict__ O, const float* __restrict__ X,
        const float* __restrict__ Wo, const float* __restrict__ bo,
        const float* __restrict__ Ws, const float* __restrict__ bs,
        float* __restrict__ out)
{
    __shared__ u64 sWo[88 * 32];   // [f][p-pair]
    __shared__ u64 sWs[NC * 32];   // [c][p-pair]
    __shared__ float sbo[DP];
    __shared__ float sbs[NC];

    const int tid = threadIdx.x;
    const int b   = blockIdx.y;
    const int o   = blockIdx.x * 256 + tid;

    for (int idx = tid; idx < 88 * 32; idx += 256) {
        int f = idx >> 5, p2 = idx & 31;
        sWo[f * 32 + p2] = pack2(Wo[(size_t)(2 * p2) * 88 + f],
                                 Wo[(size_t)(2 * p2 + 1) * 88 + f]);
    }
    for (int idx = tid; idx < NC * 32; idx += 256) {
        int c = idx >> 5, p2 = idx & 31;
        float2 w = *(const float2*)(Ws + (size_t)c * DP + 2 * p2);
        sWs[c * 32 + p2] = pack2(w.x, w.y);
    }
    if (tid < DP) sbo[tid] = bo[tid];
    if (tid < NC) sbs[tid] = bs[tid];
    __syncthreads();

    u64 P[32];
#pragma unroll
    for (int p2 = 0; p2 < 32; p2++) P[p2] = pack2(sbo[2 * p2], sbo[2 * p2 + 1]);

    const float* Ob  = O + (size_t)b * DS * NO + o;
    const float* Xb  = X + (size_t)b * DX * NO + o;
    const float* Ehb = g_Ehp + ((size_t)b * DE) * NO + o;
    const size_t SSTR = (size_t)BATCH * DE * NO;

#pragma unroll 4
    for (int f = 0; f < DS; f++) {
        float cf = Ob[(size_t)f * NO];
        u64 c2 = pack2(cf, cf);
        const u64* wrow = sWo + f * 32;
#pragma unroll
        for (int p2 = 0; p2 < 32; p2++) P[p2] = ffma2(wrow[p2], c2, P[p2]);
    }
#pragma unroll 4
    for (int f = 0; f < DX; f++) {
        float cf = Xb[(size_t)f * NO];
        u64 c2 = pack2(cf, cf);
        const u64* wrow = sWo + (DS + f) * 32;
#pragma unroll
        for (int p2 = 0; p2 < 32; p2++) P[p2] = ffma2(wrow[p2], c2, P[p2]);
    }
#pragma unroll 2
    for (int f = 0; f < DE; f++) {
        const float* ep = Ehb + (size_t)f * NO;
        float cf = 0.f;
#pragma unroll
        for (int s = 0; s < RSPLIT; s++) cf += ep[s * SSTR];
        u64 c2 = pack2(cf, cf);
        const u64* wrow = sWo + (DS + DX + f) * 32;
#pragma unroll
        for (int p2 = 0; p2 < 32; p2++) P[p2] = ffma2(wrow[p2], c2, P[p2]);
    }

    float sc[NC];
#pragma unroll
    for (int c = 0; c < NC; c++) {
        const u64* wrow = sWs + c * 32;
        u64 acc = 0ull;
#pragma unroll
        for (int p2 = 0; p2 < 32; p2++) acc = ffma2(wrow[p2], P[p2], acc);
        float2 a = unpack2(acc);
        sc[c] = a.x + a.y + sbs[c];
    }

    float mx = sc[0];
#pragma unroll
    for (int c = 1; c < NC; c++) mx = fmaxf(mx, sc[c]);
    float sum = 0.f;
#pragma unroll
    for (int c = 0; c < NC; c++) { sc[c] = expf(sc[c] - mx); sum += sc[c]; }
    float inv = 1.f / sum;
#pragma unroll
    for (int c = 0; c < NC; c++)
        out[((size_t)b * NC + c) * NO + o] = sc[c] * inv;
}

// ============================================================================
extern "C" void kernel_launch(void* const* d_in, const int* in_sizes, int n_in,
                              void* d_out, int out_size)
{
    const float* O  = (const float*)d_in[0];
    const float* Rs = (const float*)d_in[1];
    const float* Rr = (const float*)d_in[2];
    const float* Ra = (const float*)d_in[3];
    const float* X  = (const float*)d_in[4];
    const float* Wr = (const float*)d_in[5];
    const float* br = (const float*)d_in[6];
    const float* Wo = (const float*)d_in[7];
    const float* bo = (const float*)d_in[8];
    const float* Ws = (const float*)d_in[9];
    const float* bs = (const float*)d_in[10];
    float* out = (float*)d_out;
    (void)in_sizes; (void)n_in; (void)out_size;

    int smA = NO * 8 * 8 + DE * 20 * 8 + DE * 4;  // 141568 B
    cudaFuncSetAttribute(kernelA, cudaFuncAttributeMaxDynamicSharedMemorySize, smA);

    kernelA<<<dim3(NR / 512, BATCH), 512, smA>>>(O, Rs, Rr, Ra, Wr, br);
    kernelB<<<dim3(NO / 128, BATCH, RSPLIT), 128>>>(Rr);
    kernelC<<<dim3(NO / 256, BATCH), 256>>>(O, X, Wo, bo, Ws, bs, out);
}